// round 7
// baseline (speedup 1.0000x reference)
#include <cuda_runtime.h>
#include <cuda.h>
#include <cstdint>

// ---------------- problem constants ----------------
#define C_CH    321
#define D_K     512
#define P_OUT   720
#define N_B     64          // batch == GEMM M
#define BN      128         // p-tile == GEMM N
#define BK      32          // k-chunk
#define KCHUNKS (D_K / BK)  // 16
#define STAGES  3
#define NTHREADS 256

// ---------------- smem layout (TMA SW128 tiles) ----------------
// A stage: 64 rows x 128B (32 floats, SW128) = 8192 B
// B stage: 4 panels x (32 rows x 128B)       = 16384 B
#define A_STAGE_BYTES 8192
#define B_STAGE_BYTES 16384
#define CHUNK_BYTES   (A_STAGE_BYTES + B_STAGE_BYTES)   // 24576 per expect_tx
#define MBAR_OFF 0
#define A_OFF    1024
#define B_OFF    (A_OFF + STAGES * A_STAGE_BYTES)       // 25600 (1024-aligned)
#define SMEM_USED (B_OFF + STAGES * B_STAGE_BYTES)      // 74752
#define SMEM_BYTES (SMEM_USED + 1024)                   // slack for manual 1KB align

// ---------------- device helpers ----------------
__device__ __forceinline__ uint32_t smem_to_u32(const void* p) {
    uint32_t a;
    asm("{ .reg .u64 t; cvta.to.shared.u64 t, %1; cvt.u32.u64 %0, t; }" : "=r"(a) : "l"(p));
    return a;
}
// fp32 -> tf32 round-to-nearest via mantissa carry add (HMMA reads top 19 bits).
__device__ __forceinline__ uint32_t rtf32(float f) {
    return __float_as_uint(f) + 0x1000u;
}
#define MBARRIER_INIT(mb, cnt) \
    asm volatile("mbarrier.init.shared.b64 [%0], %1;" :: "r"((uint32_t)(mb)), "r"((uint32_t)(cnt)) : "memory")
#define MBARRIER_EXPECT_TX(mb, tx) \
    asm volatile("mbarrier.arrive.expect_tx.shared.b64 _, [%0], %1;" :: "r"((uint32_t)(mb)), "r"((uint32_t)(tx)) : "memory")
#define MBARRIER_WAIT_PARITY(mb, ph) do {                                               \
    uint32_t _mb = (uint32_t)(mb), _ph = (uint32_t)(ph), _done;                         \
    asm volatile("{\n\t.reg .pred p;\n\t"                                               \
        "mbarrier.try_wait.parity.acquire.cta.shared::cta.b64 p, [%1], %2;\n\t"         \
        "selp.b32 %0, 1, 0, p;\n\t}" : "=r"(_done) : "r"(_mb), "r"(_ph) : "memory");    \
    if (!_done) {                                                                       \
        asm volatile("{\n\t.reg .pred P1;\n\t"                                          \
            "WL_%=:\n\t"                                                                \
            "mbarrier.try_wait.parity.acquire.cta.shared::cta.b64 P1, [%0], %1, 0x989680;\n\t" \
            "@P1 bra.uni WD_%=;\n\t"                                                    \
            "bra.uni WL_%=;\n\t"                                                        \
            "WD_%=:\n\t}" :: "r"(_mb), "r"(_ph) : "memory");                            \
    } } while (0)
#define FENCE_PROXY_ASYNC() asm volatile("fence.proxy.async.shared::cta;" ::: "memory")
#define TMA_LOAD_2D(smem_addr, tmap, cx, cy, mb) \
    asm volatile("cp.async.bulk.tensor.2d.shared::cta.global.tile.mbarrier::complete_tx::bytes " \
        "[%0], [%1, {%2, %3}], [%4];" \
        :: "r"((uint32_t)(smem_addr)), "l"(tmap), "r"((int)(cx)), "r"((int)(cy)), \
           "r"((uint32_t)(mb)) : "memory")

__device__ __forceinline__ void mma_tf32(float* acc, const uint32_t* a, const uint32_t* b) {
    asm volatile(
        "mma.sync.aligned.m16n8k8.row.col.f32.tf32.tf32.f32 "
        "{%0,%1,%2,%3}, {%4,%5,%6,%7}, {%8,%9}, {%0,%1,%2,%3};"
        : "+f"(acc[0]), "+f"(acc[1]), "+f"(acc[2]), "+f"(acc[3])
        : "r"(a[0]), "r"(a[1]), "r"(a[2]), "r"(a[3]), "r"(b[0]), "r"(b[1]));
}

// ---------------- kernel ----------------
// CTA (blockIdx.x = p-tile, blockIdx.y = channel c):
//   out[b, c, p0:p0+128] = x[b, c, :] @ W[c, :, p0:p0+128] + bias[c, p0:p0+128]
// M=64 x N=128 x K=512 tf32 mma.sync; 8 warps (2x4, 32x32 tiles).
// Tiles loaded by TMA (cp.async.bulk.tensor.2d, SW128), 3-stage mbarrier ring.
__global__ void __launch_bounds__(NTHREADS, 3)
pc_linear_tma(const __grid_constant__ CUtensorMap tmA,
              const __grid_constant__ CUtensorMap tmB,
              const float* __restrict__ bias,
              float* __restrict__ out)
{
    extern __shared__ char smem_raw[];
    char* smem = (char*)(((uintptr_t)smem_raw + 1023) & ~(uintptr_t)1023);
    const uint32_t sbase = smem_to_u32(smem);
    float* smf = (float*)smem;

    const int tid  = threadIdx.x;
    const int lane = tid & 31;
    const int wid  = tid >> 5;
    const int gid  = lane >> 2;   // fragment group id (0..7)
    const int tig  = lane & 3;    // thread in group (0..3)
    const int wm   = wid >> 2;    // warp row (0..1) -> m0 = wm*32
    const int wn   = wid & 3;     // warp col (0..3) -> n0 = wn*32
    const int c    = blockIdx.y;
    const int p0   = blockIdx.x * BN;

    // ---- mbarrier init ----
    if (tid == 0) {
#pragma unroll
        for (int s = 0; s < STAGES; ++s) MBARRIER_INIT(sbase + MBAR_OFF + 8 * s, 1);
        FENCE_PROXY_ASYNC();
    }
    __syncthreads();

    // ---- TMA issue for one K-chunk into one stage (thread 0 only) ----
    auto issue = [&](int chunk, int stage) {
        const int k0 = chunk * BK;
        const uint32_t mb = sbase + MBAR_OFF + 8u * (uint32_t)stage;
        MBARRIER_EXPECT_TX(mb, CHUNK_BYTES);
        // A: box [32 k x 64 b] from x viewed as 2D [C*D, 64]
        TMA_LOAD_2D(sbase + A_OFF + stage * A_STAGE_BYTES, &tmA, c * D_K + k0, 0, mb);
        // B: 4 panels, box [32 p x 32 k] from W viewed as 2D [720, C*512]
#pragma unroll
        for (int j = 0; j < 4; ++j)
            TMA_LOAD_2D(sbase + B_OFF + stage * B_STAGE_BYTES + j * 4096,
                        &tmB, p0 + j * 32, c * D_K + k0, mb);
    };

    float acc[2][4][4];
#pragma unroll
    for (int mt = 0; mt < 2; ++mt)
#pragma unroll
        for (int nt = 0; nt < 4; ++nt)
#pragma unroll
            for (int q = 0; q < 4; ++q) acc[mt][nt][q] = 0.f;

    // ---- prologue: 2 chunks in flight ----
    if (tid == 0) { issue(0, 0); issue(1, 1); }

    // ---- mainloop ----
#pragma unroll 1
    for (int i = 0; i < KCHUNKS; ++i) {
        const int s = i % STAGES;
        MBARRIER_WAIT_PARITY(sbase + MBAR_OFF + 8 * s, (i / STAGES) & 1);
        __syncthreads();                       // all warps done with compute(i-1): WAR-safe
        if (tid == 0 && i + 2 < KCHUNKS) issue(i + 2, (i + 2) % STAGES);

        const float* As = smf + (A_OFF / 4) + s * (A_STAGE_BYTES / 4);
        const float* Bs = smf + (B_OFF / 4) + s * (B_STAGE_BYTES / 4);

#pragma unroll
        for (int ks = 0; ks < 4; ++ks) {
            uint32_t af[2][4], bf[4][2];
            const int c0 = ((2 * ks) ^ gid) * 4 + tig;   // SW128-swizzled A col
            const int c1 = c0 ^ 4;
#pragma unroll
            for (int mt = 0; mt < 2; ++mt) {
                const int r = wm * 32 + mt * 16 + gid;   // r & 7 == gid
                af[mt][0] = rtf32(As[r * 32 + c0]);
                af[mt][1] = rtf32(As[(r + 8) * 32 + c0]);
                af[mt][2] = rtf32(As[r * 32 + c1]);
                af[mt][3] = rtf32(As[(r + 8) * 32 + c1]);
            }
            const int kb = ks * 8 + tig;                 // kb & 7 == tig
#pragma unroll
            for (int nt = 0; nt < 4; ++nt) {
                const int colb = (nt * 8 + gid) ^ (tig << 2);   // SW128-swizzled B col
                bf[nt][0] = rtf32(Bs[wn * 1024 + kb * 32 + colb]);
                bf[nt][1] = rtf32(Bs[wn * 1024 + (kb + 4) * 32 + (colb ^ 16)]);
            }
#pragma unroll
            for (int mt = 0; mt < 2; ++mt)
#pragma unroll
                for (int nt = 0; nt < 4; ++nt)
                    mma_tf32(acc[mt][nt], af[mt], bf[nt]);
        }
    }

    // ---- epilogue: D[b][p] + bias[c][p] -> out[b][c][p] ----
#pragma unroll
    for (int nt = 0; nt < 4; ++nt) {
        const int p = p0 + wn * 32 + nt * 8 + tig * 2;
        if (p < P_OUT) {
            const float2 bv = *(const float2*)(bias + (size_t)c * P_OUT + p);
#pragma unroll
            for (int mt = 0; mt < 2; ++mt) {
                const int b0r = wm * 32 + mt * 16 + gid;
                float2 v0 = make_float2(acc[mt][nt][0] + bv.x, acc[mt][nt][1] + bv.y);
                float2 v1 = make_float2(acc[mt][nt][2] + bv.x, acc[mt][nt][3] + bv.y);
                *(float2*)(out + ((size_t)b0r * C_CH + c) * P_OUT + p)       = v0;
                *(float2*)(out + ((size_t)(b0r + 8) * C_CH + c) * P_OUT + p) = v1;
            }
        }
    }
}

// ---------------- host: tensor maps + launch ----------------
typedef CUresult (*PFN_encodeTiled)(
    CUtensorMap*, CUtensorMapDataType, cuuint32_t, void*,
    const cuuint64_t*, const cuuint64_t*, const cuuint32_t*, const cuuint32_t*,
    CUtensorMapInterleave, CUtensorMapSwizzle, CUtensorMapL2promotion,
    CUtensorMapFloatOOBfill);

extern "C" void kernel_launch(void* const* d_in, const int* in_sizes, int n_in,
                              void* d_out, int out_size) {
    const float* x  = (const float*)d_in[0];  // [64, 321, 512]
    const float* W  = (const float*)d_in[1];  // [321, 512, 720]
    const float* bi = (const float*)d_in[2];  // [321, 720]
    float* out      = (float*)d_out;          // [64, 321, 720]

    PFN_encodeTiled encode = nullptr;
    cudaDriverEntryPointQueryResult qres;
    cudaGetDriverEntryPointByVersion("cuTensorMapEncodeTiled", (void**)&encode,
                                     12000, cudaEnableDefault, &qres);

    CUtensorMap tmA{}, tmB{};
    {   // x as 2D [width = C*D, height = 64], box [32, 64], SW128
        cuuint64_t dims[2]    = {(cuuint64_t)(C_CH * D_K), (cuuint64_t)N_B};
        cuuint64_t strides[1] = {(cuuint64_t)(C_CH * D_K) * 4};
        cuuint32_t box[2]     = {32, 64};
        cuuint32_t es[2]      = {1, 1};
        encode(&tmA, CU_TENSOR_MAP_DATA_TYPE_FLOAT32, 2, (void*)x,
               dims, strides, box, es,
               CU_TENSOR_MAP_INTERLEAVE_NONE, CU_TENSOR_MAP_SWIZZLE_128B,
               CU_TENSOR_MAP_L2_PROMOTION_L2_128B, CU_TENSOR_MAP_FLOAT_OOB_FILL_NONE);
    }
    {   // W as 2D [width = 720, height = C*512], box [32, 32], SW128
        cuuint64_t dims[2]    = {(cuuint64_t)P_OUT, (cuuint64_t)(C_CH * D_K)};
        cuuint64_t strides[1] = {(cuuint64_t)P_OUT * 4};
        cuuint32_t box[2]     = {32, 32};
        cuuint32_t es[2]      = {1, 1};
        encode(&tmB, CU_TENSOR_MAP_DATA_TYPE_FLOAT32, 2, (void*)W,
               dims, strides, box, es,
               CU_TENSOR_MAP_INTERLEAVE_NONE, CU_TENSOR_MAP_SWIZZLE_128B,
               CU_TENSOR_MAP_L2_PROMOTION_L2_128B, CU_TENSOR_MAP_FLOAT_OOB_FILL_NONE);
    }

    cudaFuncSetAttribute(pc_linear_tma,
                         cudaFuncAttributeMaxDynamicSharedMemorySize, SMEM_BYTES);
    dim3 grid((P_OUT + BN - 1) / BN, C_CH);   // 6 x 321 = 1926 CTAs
    pc_linear_tma<<<grid, NTHREADS, SMEM_BYTES>>>(tmA, tmB, bi, out);
}

// round 8
// speedup vs baseline: 1.0573x; 1.0573x over previous
#include <cuda_runtime.h>
#include <cstdint>

// ---------------- problem constants ----------------
#define C_CH    321
#define D_K     512
#define P_OUT   720
#define N_B     64          // batch == GEMM M
#define BN      128         // p-tile == GEMM N
#define BK      16          // k-chunk
#define KCHUNKS (D_K / BK)  // 32
#define STAGES  3
#define NTHREADS 256

// ---------------- smem layout ----------------
// A: 64 rows x 16 floats, padded stride 20 (bank-conflict-free fragment reads).
// B: 16 rows x 128 floats, padded stride 136.
#define A_STRIDE 20
#define B_STRIDE 136
#define A_STAGE_FLOATS (N_B * A_STRIDE)       // 1280
#define A_STAGE_BYTES  (A_STAGE_FLOATS * 4)   // 5120
#define B_STAGE_BYTES  (BK * B_STRIDE * 4)    // 8704
#define B_BASE         (STAGES * A_STAGE_BYTES)            // 15360
#define SMEM_BYTES     (B_BASE + STAGES * B_STAGE_BYTES)   // 41472 (40.5 KB) -> 4 CTAs/SM

// ---------------- helpers ----------------
// fp32 -> tf32 round-to-nearest via mantissa carry add (HMMA reads top 19 bits).
__device__ __forceinline__ uint32_t rtf32(float f) {
    return __float_as_uint(f) + 0x1000u;
}
__device__ __forceinline__ uint32_t smem_to_u32(const void* p) {
    uint32_t a;
    asm("{ .reg .u64 t; cvta.to.shared.u64 t, %1; cvt.u32.u64 %0, t; }" : "=r"(a) : "l"(p));
    return a;
}
#define CP_ASYNC16(dst, src) \
    asm volatile("cp.async.cg.shared.global [%0], [%1], 16;" :: "r"(dst), "l"(src))
#define CP_ASYNC16_Z(dst, src, sz) \
    asm volatile("cp.async.cg.shared.global [%0], [%1], 16, %2;" :: "r"(dst), "l"(src), "r"(sz))
#define CP_COMMIT()  asm volatile("cp.async.commit_group;" ::: "memory")
#define CP_WAIT1()   asm volatile("cp.async.wait_group 1;" ::: "memory")

__device__ __forceinline__ void mma_tf32(float* acc, const uint32_t* a, const uint32_t* b) {
    asm volatile(
        "mma.sync.aligned.m16n8k8.row.col.f32.tf32.tf32.f32 "
        "{%0,%1,%2,%3}, {%4,%5,%6,%7}, {%8,%9}, {%0,%1,%2,%3};"
        : "+f"(acc[0]), "+f"(acc[1]), "+f"(acc[2]), "+f"(acc[3])
        : "r"(a[0]), "r"(a[1]), "r"(a[2]), "r"(a[3]), "r"(b[0]), "r"(b[1]));
}

// ---------------- kernel ----------------
// CTA (blockIdx.x = p-tile, blockIdx.y = channel c):
//   out[b, c, p0:p0+128] = x[b, c, :] @ W[c, :, p0:p0+128] + bias[c, p0:p0+128]
// M=64 x N=128 x K=512 tf32 mma.sync; 8 warps (2x4, 32x32 tiles);
// 3-stage cp.async pipeline (BK=16), one barrier per chunk; 4 CTAs/SM.
__global__ void __launch_bounds__(NTHREADS, 4)
pc_linear_mma(const float* __restrict__ x,
              const float* __restrict__ W,
              const float* __restrict__ bias,
              float* __restrict__ out)
{
    extern __shared__ float sm[];
    const uint32_t sbase = smem_to_u32(sm);

    const int tid  = threadIdx.x;
    const int lane = tid & 31;
    const int wid  = tid >> 5;
    const int gid  = lane >> 2;   // fragment group id (0..7)
    const int tig  = lane & 3;    // thread in group (0..3)
    const int wm   = wid >> 2;    // warp row (0..1) -> m0 = wm*32
    const int wn   = wid & 3;     // warp col (0..3) -> n0 = wn*32
    const int c    = blockIdx.y;
    const int p0   = blockIdx.x * BN;

    const float* xc = x + (size_t)c * D_K;
    const float* Wc = W + (size_t)c * ((size_t)D_K * P_OUT);

    // ---- cp.async issue for one K-chunk into one stage ----
    auto issue = [&](int chunk, int stage) {
        const int k0 = chunk * BK;
        // A tile: 64 rows x 16 floats (stride 20) -> 256 x 16B, one per thread
        const uint32_t abase = sbase + (uint32_t)stage * A_STAGE_BYTES;
        {
            const int r    = tid >> 2;         // batch row
            const int col4 = (tid & 3) * 4;    // k offset (16B chunk)
            const float* src = xc + (size_t)r * (C_CH * D_K) + k0 + col4;
            CP_ASYNC16(abase + (uint32_t)(r * A_STRIDE + col4) * 4, src);
        }
        // B tile: 16 rows x 128 floats (stride 136) -> 512 x 16B, two per thread
        const uint32_t bbase = sbase + B_BASE + (uint32_t)stage * B_STAGE_BYTES;
#pragma unroll
        for (int j = 0; j < 2; ++j) {
            const int id  = tid + j * NTHREADS;
            const int r   = id >> 5;          // k row (0..15)
            const int col = (id & 31) * 4;    // p offset
            const float* src = Wc + (size_t)(k0 + r) * P_OUT + p0 + col;
            const int sz = (p0 + col < P_OUT) ? 16 : 0;
            CP_ASYNC16_Z(bbase + (uint32_t)(r * B_STRIDE + col) * 4, src, sz);
        }
    };

    float acc[2][4][4];
#pragma unroll
    for (int mt = 0; mt < 2; ++mt)
#pragma unroll
        for (int nt = 0; nt < 4; ++nt)
#pragma unroll
            for (int q = 0; q < 4; ++q) acc[mt][nt][q] = 0.f;

    // ---- prologue: 2 chunks in flight ----
    issue(0, 0); CP_COMMIT();
    issue(1, 1); CP_COMMIT();

    // ---- mainloop: ONE barrier per chunk ----
#pragma unroll 1
    for (int i = 0; i < KCHUNKS; ++i) {
        CP_WAIT1();               // chunk i landed
        __syncthreads();          // publish stage i; proves compute(i-1) done (WAR-safe)
        if (i + 2 < KCHUNKS) issue(i + 2, (i + 2) % STAGES);
        CP_COMMIT();              // commit every iter (possibly empty) keeps ledger exact

        const float* As = sm + (size_t)(i % STAGES) * A_STAGE_FLOATS;
        const float* Bs = sm + (B_BASE / 4) + (size_t)(i % STAGES) * (B_STAGE_BYTES / 4);

#pragma unroll
        for (int ks = 0; ks < 2; ++ks) {
            uint32_t af[2][4], bf[4][2];
            const int ca = ks * 8 + tig;
#pragma unroll
            for (int mt = 0; mt < 2; ++mt) {
                const int r = wm * 32 + mt * 16 + gid;
                af[mt][0] = rtf32(As[r * A_STRIDE + ca]);
                af[mt][1] = rtf32(As[(r + 8) * A_STRIDE + ca]);
                af[mt][2] = rtf32(As[r * A_STRIDE + ca + 4]);
                af[mt][3] = rtf32(As[(r + 8) * A_STRIDE + ca + 4]);
            }
            const int kb = ks * 8 + tig;
#pragma unroll
            for (int nt = 0; nt < 4; ++nt) {
                const int col = wn * 32 + nt * 8 + gid;
                bf[nt][0] = rtf32(Bs[kb * B_STRIDE + col]);
                bf[nt][1] = rtf32(Bs[(kb + 4) * B_STRIDE + col]);
            }
#pragma unroll
            for (int mt = 0; mt < 2; ++mt)
#pragma unroll
                for (int nt = 0; nt < 4; ++nt)
                    mma_tf32(acc[mt][nt], af[mt], bf[nt]);
        }
    }

    // ---- epilogue: D[b][p] + bias[c][p] -> out[b][c][p] ----
#pragma unroll
    for (int nt = 0; nt < 4; ++nt) {
        const int p = p0 + wn * 32 + nt * 8 + tig * 2;
        if (p < P_OUT) {
            const float2 bv = *(const float2*)(bias + (size_t)c * P_OUT + p);
#pragma unroll
            for (int mt = 0; mt < 2; ++mt) {
                const int b0r = wm * 32 + mt * 16 + gid;
                float2 v0 = make_float2(acc[mt][nt][0] + bv.x, acc[mt][nt][1] + bv.y);
                float2 v1 = make_float2(acc[mt][nt][2] + bv.x, acc[mt][nt][3] + bv.y);
                *(float2*)(out + ((size_t)b0r * C_CH + c) * P_OUT + p)       = v0;
                *(float2*)(out + ((size_t)(b0r + 8) * C_CH + c) * P_OUT + p) = v1;
            }
        }
    }
}

// ---------------- launch ----------------
extern "C" void kernel_launch(void* const* d_in, const int* in_sizes, int n_in,
                              void* d_out, int out_size) {
    const float* x  = (const float*)d_in[0];  // [64, 321, 512]
    const float* W  = (const float*)d_in[1];  // [321, 512, 720]
    const float* bi = (const float*)d_in[2];  // [321, 720]
    float* out      = (float*)d_out;          // [64, 321, 720]

    cudaFuncSetAttribute(pc_linear_mma,
                         cudaFuncAttributeMaxDynamicSharedMemorySize, SMEM_BYTES);
    dim3 grid((P_OUT + BN - 1) / BN, C_CH);   // 6 x 321 = 1926 CTAs
    pc_linear_mma<<<grid, NTHREADS, SMEM_BYTES>>>(x, W, bi, out);
}

// round 9
// speedup vs baseline: 1.1939x; 1.1291x over previous
#include <cuda_runtime.h>
#include <cstdint>

// ---------------- problem constants ----------------
#define C_CH    321
#define D_K     512
#define P_OUT   720
#define N_B     64          // batch == GEMM M
#define BN      128         // p-tile == GEMM N
#define BK      32          // k-chunk
#define KCHUNKS (D_K / BK)  // 16
#define STAGES  3
#define NTHREADS 256

// ---------------- smem layout ----------------
// A: 64 rows x 32 floats (128B rows), XOR-16B swizzle (ldmatrix-ready, conflict-free).
// B: 32 rows x 136 floats (padded, conflict-free scalar LDS).
#define A_STAGE_BYTES  8192
#define B_STRIDE 136
#define B_STAGE_BYTES  (BK * B_STRIDE * 4)   // 17408
#define B_BASE         (STAGES * A_STAGE_BYTES)            // 24576
#define SMEM_BYTES     (B_BASE + STAGES * B_STAGE_BYTES)   // 76800 (75 KB) -> 3 CTAs/SM

// ---------------- helpers ----------------
__device__ __forceinline__ uint32_t smem_to_u32(const void* p) {
    uint32_t a;
    asm("{ .reg .u64 t; cvta.to.shared.u64 t, %1; cvt.u32.u64 %0, t; }" : "=r"(a) : "l"(p));
    return a;
}
// fp32 -> tf32 round-to-nearest via mantissa carry add (HMMA reads top 19 bits).
__device__ __forceinline__ uint32_t rtf32(float f) {
    return __float_as_uint(f) + 0x1000u;
}
#define CP_ASYNC16(dst, src) \
    asm volatile("cp.async.cg.shared.global [%0], [%1], 16;" :: "r"(dst), "l"(src))
#define CP_ASYNC16_Z(dst, src, sz) \
    asm volatile("cp.async.cg.shared.global [%0], [%1], 16, %2;" :: "r"(dst), "l"(src), "r"(sz))
#define CP_COMMIT()  asm volatile("cp.async.commit_group;" ::: "memory")
#define CP_WAIT1()   asm volatile("cp.async.wait_group 1;" ::: "memory")
#define LDMATRIX_X4(r0, r1, r2, r3, addr) \
    asm volatile("ldmatrix.sync.aligned.m8n8.x4.shared.b16 {%0,%1,%2,%3}, [%4];" \
        : "=r"(r0), "=r"(r1), "=r"(r2), "=r"(r3) : "r"(addr))

__device__ __forceinline__ void mma_tf32(float* acc, const uint32_t* a, const uint32_t* b) {
    asm volatile(
        "mma.sync.aligned.m16n8k8.row.col.f32.tf32.tf32.f32 "
        "{%0,%1,%2,%3}, {%4,%5,%6,%7}, {%8,%9}, {%0,%1,%2,%3};"
        : "+f"(acc[0]), "+f"(acc[1]), "+f"(acc[2]), "+f"(acc[3])
        : "r"(a[0]), "r"(a[1]), "r"(a[2]), "r"(a[3]), "r"(b[0]), "r"(b[1]));
}

// ---------------- kernel ----------------
// CTA (blockIdx.x = p-tile, blockIdx.y = channel c):
//   out[b, c, p0:p0+128] = x[b, c, :] @ W[c, :, p0:p0+128] + bias[c, p0:p0+128]
// M=64 x N=128 x K=512 tf32 mma.sync; 8 warps (2x4, 32x32 tiles);
// A fragments via ldmatrix.x4 (x truncated to tf32), B via padded LDS (W rounded);
// 3-stage cp.async pipeline, one barrier per chunk; 3 CTAs/SM.
__global__ void __launch_bounds__(NTHREADS, 3)
pc_linear_mma(const float* __restrict__ x,
              const float* __restrict__ W,
              const float* __restrict__ bias,
              float* __restrict__ out)
{
    extern __shared__ float sm[];
    const uint32_t sbase = smem_to_u32(sm);

    const int tid  = threadIdx.x;
    const int lane = tid & 31;
    const int wid  = tid >> 5;
    const int gid  = lane >> 2;   // fragment group id (0..7)
    const int tig  = lane & 3;    // thread in group (0..3)
    const int wm   = wid >> 2;    // warp row (0..1) -> m0 = wm*32
    const int wn   = wid & 3;     // warp col (0..3) -> n0 = wn*32
    const int c    = blockIdx.y;
    const int p0   = blockIdx.x * BN;

    const float* xc = x + (size_t)c * D_K;
    const float* Wc = W + (size_t)c * ((size_t)D_K * P_OUT);

    // ---- per-lane ldmatrix offsets (A tile, mt=0; mt=1 adds 2048B = 16 rows) ----
    // lane l supplies row (l&7)(+8 if l&8) of matrices {a0,a1,a2,a3};
    // matrices 2,3 (l>=16) take the +4-float column half.
    uint32_t foff[4];
    {
        const int m0  = wm * 32 + (lane & 7) + (lane & 8);
        const int swz = (m0 & 7) * 16;
        const int hi  = (lane >> 4) * 16;
#pragma unroll
        for (int ks = 0; ks < 4; ++ks)
            foff[ks] = (uint32_t)(m0 * 128 + ((ks * 32 + hi) ^ swz));
    }

    // ---- cp.async issue for one K-chunk into one stage ----
    auto issue = [&](int chunk, int stage) {
        const int k0 = chunk * BK;
        // A tile: 64 rows x 32 floats, 16B-chunk swizzle: chunk ^= (row & 7)
        const uint32_t abase = sbase + (uint32_t)stage * A_STAGE_BYTES;
#pragma unroll
        for (int i = 0; i < 2; ++i) {
            const int id   = tid + i * NTHREADS;
            const int r    = id >> 3;          // batch row
            const int col4 = (id & 7) * 4;     // k offset (16B chunk)
            const float* src = xc + (size_t)r * (C_CH * D_K) + k0 + col4;
            const uint32_t foffA = (uint32_t)(r * 32 + (col4 ^ ((r & 7) * 4)));
            CP_ASYNC16(abase + foffA * 4, src);
        }
        // B tile: 32 rows x 128 floats (pad 136); zero-fill OOB p
        const uint32_t bbase = sbase + B_BASE + (uint32_t)stage * B_STAGE_BYTES;
#pragma unroll
        for (int j = 0; j < 4; ++j) {
            const int id  = tid + j * NTHREADS;
            const int r   = id >> 5;          // k row
            const int col = (id & 31) * 4;    // p offset
            const float* src = Wc + (size_t)(k0 + r) * P_OUT + p0 + col;
            const int sz = (p0 + col < P_OUT) ? 16 : 0;
            CP_ASYNC16_Z(bbase + (uint32_t)(r * B_STRIDE + col) * 4, src, sz);
        }
    };

    float acc[2][4][4];
#pragma unroll
    for (int mt = 0; mt < 2; ++mt)
#pragma unroll
        for (int nt = 0; nt < 4; ++nt)
#pragma unroll
            for (int q = 0; q < 4; ++q) acc[mt][nt][q] = 0.f;

    // ---- prologue: 2 chunks in flight ----
    issue(0, 0); CP_COMMIT();
    issue(1, 1); CP_COMMIT();

    // ---- mainloop: ONE barrier per chunk ----
#pragma unroll 1
    for (int i = 0; i < KCHUNKS; ++i) {
        CP_WAIT1();               // chunk i landed
        __syncthreads();          // publish stage i; proves compute(i-1) done (WAR-safe)
        if (i + 2 < KCHUNKS) issue(i + 2, (i + 2) % STAGES);
        CP_COMMIT();              // commit every iter (possibly empty) keeps ledger exact

        const uint32_t As_b = sbase + (uint32_t)(i % STAGES) * A_STAGE_BYTES;
        const float*   Bs   = sm + (B_BASE / 4) + (size_t)(i % STAGES) * (B_STAGE_BYTES / 4);

#pragma unroll
        for (int ks = 0; ks < 4; ++ks) {
            uint32_t af[2][4], bf[4][2];
            const uint32_t a0 = As_b + foff[ks];
            LDMATRIX_X4(af[0][0], af[0][1], af[0][2], af[0][3], a0);
            LDMATRIX_X4(af[1][0], af[1][1], af[1][2], af[1][3], a0 + 2048);

            const int kb = ks * 8 + tig;
#pragma unroll
            for (int nt = 0; nt < 4; ++nt) {
                const int col = wn * 32 + nt * 8 + gid;
                bf[nt][0] = rtf32(Bs[kb * B_STRIDE + col]);
                bf[nt][1] = rtf32(Bs[(kb + 4) * B_STRIDE + col]);
            }
#pragma unroll
            for (int mt = 0; mt < 2; ++mt)
#pragma unroll
                for (int nt = 0; nt < 4; ++nt)
                    mma_tf32(acc[mt][nt], af[mt], bf[nt]);
        }
    }

    // ---- epilogue: D[b][p] + bias[c][p] -> out[b][c][p] ----
#pragma unroll
    for (int nt = 0; nt < 4; ++nt) {
        const int p = p0 + wn * 32 + nt * 8 + tig * 2;
        if (p < P_OUT) {
            const float2 bv = *(const float2*)(bias + (size_t)c * P_OUT + p);
#pragma unroll
            for (int mt = 0; mt < 2; ++mt) {
                const int b0r = wm * 32 + mt * 16 + gid;
                float2 v0 = make_float2(acc[mt][nt][0] + bv.x, acc[mt][nt][1] + bv.y);
                float2 v1 = make_float2(acc[mt][nt][2] + bv.x, acc[mt][nt][3] + bv.y);
                *(float2*)(out + ((size_t)b0r * C_CH + c) * P_OUT + p)       = v0;
                *(float2*)(out + ((size_t)(b0r + 8) * C_CH + c) * P_OUT + p) = v1;
            }
        }
    }
}

// ---------------- launch ----------------
extern "C" void kernel_launch(void* const* d_in, const int* in_sizes, int n_in,
                              void* d_out, int out_size) {
    const float* x  = (const float*)d_in[0];  // [64, 321, 512]
    const float* W  = (const float*)d_in[1];  // [321, 512, 720]
    const float* bi = (const float*)d_in[2];  // [321, 720]
    float* out      = (float*)d_out;          // [64, 321, 720]

    cudaFuncSetAttribute(pc_linear_mma,
                         cudaFuncAttributeMaxDynamicSharedMemorySize, SMEM_BYTES);
    dim3 grid((P_OUT + BN - 1) / BN, C_CH);   // 6 x 321 = 1926 CTAs
    pc_linear_mma<<<grid, NTHREADS, SMEM_BYTES>>>(x, W, bi, out);
}

// round 10
// speedup vs baseline: 1.2185x; 1.0206x over previous
#include <cuda_runtime.h>
#include <cstdint>

// ---------------- problem constants ----------------
#define C_CH    321
#define D_K     512
#define P_OUT   720
#define N_B     64          // batch == GEMM M
#define BN      128         // p-tile == GEMM N
#define BK      32          // k-chunk
#define KCHUNKS (D_K / BK)  // 16
#define STAGES  3
#define NTHREADS 256

// ---------------- smem layout ----------------
// A: 64 rows x 32 floats (128B rows), XOR-16B swizzle (ldmatrix-ready, conflict-free).
// B: 32 rows x 136 floats (padded, conflict-free scalar LDS).
#define A_STAGE_BYTES  8192
#define B_STRIDE 136
#define B_STAGE_BYTES  (BK * B_STRIDE * 4)   // 17408
#define B_BASE         (STAGES * A_STAGE_BYTES)            // 24576
#define SMEM_BYTES     (B_BASE + STAGES * B_STAGE_BYTES)   // 76800 (75 KB) -> 3 CTAs/SM

// ---------------- helpers ----------------
__device__ __forceinline__ uint32_t smem_to_u32(const void* p) {
    uint32_t a;
    asm("{ .reg .u64 t; cvta.to.shared.u64 t, %1; cvt.u32.u64 %0, t; }" : "=r"(a) : "l"(p));
    return a;
}
// fp32 -> tf32 round-to-nearest via mantissa carry add (HMMA reads top 19 bits).
__device__ __forceinline__ uint32_t rtf32(float f) {
    return __float_as_uint(f) + 0x1000u;
}
#define CP_ASYNC16(dst, src) \
    asm volatile("cp.async.cg.shared.global [%0], [%1], 16;" :: "r"(dst), "l"(src))
#define CP_ASYNC16_Z(dst, src, sz) \
    asm volatile("cp.async.cg.shared.global [%0], [%1], 16, %2;" :: "r"(dst), "l"(src), "r"(sz))
#define CP_COMMIT()  asm volatile("cp.async.commit_group;" ::: "memory")
#define CP_WAIT1()   asm volatile("cp.async.wait_group 1;" ::: "memory")
#define LDMATRIX_X4(r0, r1, r2, r3, addr) \
    asm volatile("ldmatrix.sync.aligned.m8n8.x4.shared.b16 {%0,%1,%2,%3}, [%4];" \
        : "=r"(r0), "=r"(r1), "=r"(r2), "=r"(r3) : "r"(addr))

__device__ __forceinline__ void mma_tf32(float* acc, const uint32_t* a, const uint32_t* b) {
    asm volatile(
        "mma.sync.aligned.m16n8k8.row.col.f32.tf32.tf32.f32 "
        "{%0,%1,%2,%3}, {%4,%5,%6,%7}, {%8,%9}, {%0,%1,%2,%3};"
        : "+f"(acc[0]), "+f"(acc[1]), "+f"(acc[2]), "+f"(acc[3])
        : "r"(a[0]), "r"(a[1]), "r"(a[2]), "r"(a[3]), "r"(b[0]), "r"(b[1]));
}

// ---------------- kernel ----------------
// CTA (blockIdx.x = p-tile, blockIdx.y = channel c):
//   out[b, c, p0:p0+128] = x[b, c, :] @ W[c, :, p0:p0+128] + bias[c, p0:p0+128]
// M=64 x N=128 x K=512 tf32 mma.sync; 8 warps in 1x8 grid (warp tile 64x16):
// halves per-warp B fragment traffic; A via ldmatrix.x4 (x truncated to tf32),
// B via padded LDS (W rounded). 3-stage cp.async pipeline, 1 barrier/chunk, 3 CTAs/SM.
__global__ void __launch_bounds__(NTHREADS, 3)
pc_linear_mma(const float* __restrict__ x,
              const float* __restrict__ W,
              const float* __restrict__ bias,
              float* __restrict__ out)
{
    extern __shared__ float sm[];
    const uint32_t sbase = smem_to_u32(sm);

    const int tid  = threadIdx.x;
    const int lane = tid & 31;
    const int wid  = tid >> 5;    // warp col (0..7) -> n0 = wid*16
    const int gid  = lane >> 2;   // fragment group id (0..7)
    const int tig  = lane & 3;    // thread in group (0..3)
    const int c    = blockIdx.y;
    const int p0   = blockIdx.x * BN;

    const float* xc = x + (size_t)c * D_K;
    const float* Wc = W + (size_t)c * ((size_t)D_K * P_OUT);

    // ---- per-lane ldmatrix offsets (A tile, mt=0; mt adds 2048B = 16 rows) ----
    uint32_t foff[4];
    {
        const int m0  = (lane & 7) + (lane & 8);
        const int swz = (m0 & 7) * 16;
        const int hi  = (lane >> 4) * 16;
#pragma unroll
        for (int ks = 0; ks < 4; ++ks)
            foff[ks] = (uint32_t)(m0 * 128 + ((ks * 32 + hi) ^ swz));
    }

    // ---- cp.async issue for one K-chunk into one stage ----
    auto issue = [&](int chunk, int stage) {
        const int k0 = chunk * BK;
        // A tile: 64 rows x 32 floats, 16B-chunk swizzle: chunk ^= (row & 7)
        const uint32_t abase = sbase + (uint32_t)stage * A_STAGE_BYTES;
#pragma unroll
        for (int i = 0; i < 2; ++i) {
            const int id   = tid + i * NTHREADS;
            const int r    = id >> 3;          // batch row
            const int col4 = (id & 7) * 4;     // k offset (16B chunk)
            const float* src = xc + (size_t)r * (C_CH * D_K) + k0 + col4;
            const uint32_t foffA = (uint32_t)(r * 32 + (col4 ^ ((r & 7) * 4)));
            CP_ASYNC16(abase + foffA * 4, src);
        }
        // B tile: 32 rows x 128 floats (pad 136); zero-fill OOB p
        const uint32_t bbase = sbase + B_BASE + (uint32_t)stage * B_STAGE_BYTES;
#pragma unroll
        for (int j = 0; j < 4; ++j) {
            const int id  = tid + j * NTHREADS;
            const int r   = id >> 5;          // k row
            const int col = (id & 31) * 4;    // p offset
            const float* src = Wc + (size_t)(k0 + r) * P_OUT + p0 + col;
            const int sz = (p0 + col < P_OUT) ? 16 : 0;
            CP_ASYNC16_Z(bbase + (uint32_t)(r * B_STRIDE + col) * 4, src, sz);
        }
    };

    float acc[4][2][4];   // mt x nt x quad
#pragma unroll
    for (int mt = 0; mt < 4; ++mt)
#pragma unroll
        for (int nt = 0; nt < 2; ++nt)
#pragma unroll
            for (int q = 0; q < 4; ++q) acc[mt][nt][q] = 0.f;

    // ---- prologue: 2 chunks in flight ----
    issue(0, 0); CP_COMMIT();
    issue(1, 1); CP_COMMIT();

    // ---- mainloop: ONE barrier per chunk ----
#pragma unroll 1
    for (int i = 0; i < KCHUNKS; ++i) {
        CP_WAIT1();               // chunk i landed
        __syncthreads();          // publish stage i; proves compute(i-1) done (WAR-safe)
        if (i + 2 < KCHUNKS) issue(i + 2, (i + 2) % STAGES);
        CP_COMMIT();              // commit every iter (possibly empty) keeps ledger exact

        const uint32_t As_b = sbase + (uint32_t)(i % STAGES) * A_STAGE_BYTES;
        const float*   Bs   = sm + (B_BASE / 4) + (size_t)(i % STAGES) * (B_STAGE_BYTES / 4);

#pragma unroll
        for (int ks = 0; ks < 4; ++ks) {
            uint32_t af[4][4], bf[2][2];
            const uint32_t a0 = As_b + foff[ks];
#pragma unroll
            for (int mt = 0; mt < 4; ++mt)
                LDMATRIX_X4(af[mt][0], af[mt][1], af[mt][2], af[mt][3],
                            a0 + (uint32_t)mt * 2048);

            const int kb = ks * 8 + tig;
#pragma unroll
            for (int nt = 0; nt < 2; ++nt) {
                const int col = wid * 16 + nt * 8 + gid;
                bf[nt][0] = rtf32(Bs[kb * B_STRIDE + col]);
                bf[nt][1] = rtf32(Bs[(kb + 4) * B_STRIDE + col]);
            }
#pragma unroll
            for (int mt = 0; mt < 4; ++mt)
#pragma unroll
                for (int nt = 0; nt < 2; ++nt)
                    mma_tf32(acc[mt][nt], af[mt], bf[nt]);
        }
    }

    // ---- epilogue: D[b][p] + bias[c][p] -> out[b][c][p] ----
#pragma unroll
    for (int nt = 0; nt < 2; ++nt) {
        const int p = p0 + wid * 16 + nt * 8 + tig * 2;
        if (p < P_OUT) {
            const float2 bv = *(const float2*)(bias + (size_t)c * P_OUT + p);
#pragma unroll
            for (int mt = 0; mt < 4; ++mt) {
                const int b0r = mt * 16 + gid;
                float2 v0 = make_float2(acc[mt][nt][0] + bv.x, acc[mt][nt][1] + bv.y);
                float2 v1 = make_float2(acc[mt][nt][2] + bv.x, acc[mt][nt][3] + bv.y);
                *(float2*)(out + ((size_t)b0r * C_CH + c) * P_OUT + p)       = v0;
                *(float2*)(out + ((size_t)(b0r + 8) * C_CH + c) * P_OUT + p) = v1;
            }
        }
    }
}

// ---------------- launch ----------------
extern "C" void kernel_launch(void* const* d_in, const int* in_sizes, int n_in,
                              void* d_out, int out_size) {
    const float* x  = (const float*)d_in[0];  // [64, 321, 512]
    const float* W  = (const float*)d_in[1];  // [321, 512, 720]
    const float* bi = (const float*)d_in[2];  // [321, 720]
    float* out      = (float*)d_out;          // [64, 321, 720]

    cudaFuncSetAttribute(pc_linear_mma,
                         cudaFuncAttributeMaxDynamicSharedMemorySize, SMEM_BYTES);
    dim3 grid((P_OUT + BN - 1) / BN, C_CH);   // 6 x 321 = 1926 CTAs
    pc_linear_mma<<<grid, NTHREADS, SMEM_BYTES>>>(x, W, bi, out);
}